// round 9
// baseline (speedup 1.0000x reference)
#include <cuda_runtime.h>
#include <math_constants.h>
#include <cstdint>

// SubsetOperator soft k-hot (K=16, TAU=1), exp-domain, fixed shift:
//   e = exp(s0 - 10); repeat K: p = e/Z; khot += p; e *= (1-p)
// 2-iteration bodies: each body needs (Z, S2=sum e^2) of its entry state:
//   p_even = 1/Z (direct sum), p_odd = 1/(Z - S2/Z) (one exact step).
// Symmetric redundant reduction: every warp butterflies its own (Z,S2), lane0
// STS float2, ONE barrier per body, then every warp redundantly cross-reduces
// 16 partials + rcp. No producer warp, no publish, 9 barriers/row.

#define ROWS 4096
#define NCOL 8192
#define THREADS 512
#define PAIRS 8
#define GRID 296

typedef unsigned long long u64;
typedef unsigned int u32;

#define MUL2(d,a,b)    asm("mul.rn.f32x2 %0, %1, %2;"     : "=l"(d) : "l"(a), "l"(b))
#define ADD2(d,a,b)    asm("add.rn.f32x2 %0, %1, %2;"     : "=l"(d) : "l"(a), "l"(b))
#define FMA2(d,a,b,c)  asm("fma.rn.f32x2 %0, %1, %2, %3;" : "=l"(d) : "l"(a), "l"(b), "l"(c))
#define PACK2(d,lo,hi)   asm("mov.b64 %0, {%1, %2};" : "=l"(d) : "f"(lo), "f"(hi))
#define UNPACK2(lo,hi,s) asm("mov.b64 {%0, %1}, %2;" : "=f"(lo), "=f"(hi) : "l"(s))

__device__ __forceinline__ float rcp_fast(float x) {
    float r; asm("rcp.approx.f32 %0, %1;" : "=f"(r) : "f"(x)); return r;
}
__device__ __forceinline__ float ex2_fast(float x) {
    float r; asm("ex2.approx.f32 %0, %1;" : "=f"(r) : "f"(x)); return r;
}

__device__ __forceinline__ void cp16(u32 dst, const void* src) {
    asm volatile("cp.async.cg.shared.global [%0], [%1], 16;" :: "r"(dst), "l"(src));
}

__device__ __forceinline__ void prefetch_row(const float* s, const float* gg,
                                             int row, float* tile, int tid, bool valid) {
    if (valid) {
        const float4* s4 = (const float4*)(s + (size_t)row * NCOL);
        const float4* g4 = (const float4*)(gg + (size_t)row * NCOL);
        u32 ds = (u32)__cvta_generic_to_shared(tile);
#pragma unroll
        for (int c = 0; c < 4; c++) {
            cp16(ds + (u32)(tid + c * THREADS) * 16u,                  s4 + tid + c * THREADS);
            cp16(ds + (u32)NCOL * 4u + (u32)(tid + c * THREADS) * 16u, g4 + tid + c * THREADS);
        }
    }
    asm volatile("cp.async.commit_group;");
}

// Intra-warp butterfly of (zf, s2f), lane0 stores float2 into red[wid].
__device__ __forceinline__ void warp_partial_out(float zf, float s2f,
                                                 float2* red, int wid, int lane) {
#pragma unroll
    for (int o = 16; o > 0; o >>= 1) {
        zf  += __shfl_xor_sync(0xffffffffu, zf, o);
        s2f += __shfl_xor_sync(0xffffffffu, s2f, o);
    }
    if (lane == 0) { float2 t; t.x = zf; t.y = s2f; red[wid] = t; }
}

__global__ void __launch_bounds__(THREADS, 2)
subset_op_kernel(const float* __restrict__ scores,
                 const float* __restrict__ g,
                 float* __restrict__ out) {
    extern __shared__ __align__(16) float tile[];     // 2*NCOL floats = 64KB
    __shared__ __align__(16) float2 red[2][16];

    const int tid  = threadIdx.x;
    const int lane = tid & 31;
    const int wid  = tid >> 5;
    const float L2E = 1.4426950408889634f;
    const float CC  = -10.0f * L2E;

    int row = blockIdx.x;
    prefetch_row(scores, g, row, tile, tid, true);

    for (; row < ROWS; row += GRID) {
        asm volatile("cp.async.wait_group 0;");
        __syncthreads();

        // ---- prologue: exp + (Z, S2) partials of e_0 ----
        u64 e[PAIRS], nk[PAIRS];
        const float4* ts4 = (const float4*)tile;
        const float4* tg4 = (const float4*)(tile + NCOL);
        u64 z2 = 0ull, s22 = 0ull;
#pragma unroll
        for (int c = 0; c < 4; c++) {
            const int i4 = tid + c * THREADS;
            float4 a = ts4[i4];
            float4 b = tg4[i4];
            float e0 = ex2_fast(fmaf(a.x + b.x, L2E, CC));
            float e1 = ex2_fast(fmaf(a.y + b.y, L2E, CC));
            float e2 = ex2_fast(fmaf(a.z + b.z, L2E, CC));
            float e3 = ex2_fast(fmaf(a.w + b.w, L2E, CC));
            PACK2(e[2 * c],     e0, e1);
            PACK2(e[2 * c + 1], e2, e3);
            nk[2 * c] = 0ull; nk[2 * c + 1] = 0ull;
            ADD2(z2, z2, e[2 * c]);
            ADD2(z2, z2, e[2 * c + 1]);
            FMA2(s22, e[2 * c],     e[2 * c],     s22);
            FMA2(s22, e[2 * c + 1], e[2 * c + 1], s22);
        }
        // tile consumed -> prefetch next row under compute
        prefetch_row(scores, g, row + GRID, tile, tid, (row + GRID) < ROWS);

        {
            float lo, hi, zf, s2f;
            UNPACK2(lo, hi, z2);  zf  = lo + hi;
            UNPACK2(lo, hi, s22); s2f = lo + hi;
            warp_partial_out(zf, s2f, red[0], wid, lane);
        }
        __syncthreads();

        // ---- 8 bodies x 2 iterations ----
#pragma unroll
        for (int r = 0; r < 8; r++) {
            // Redundant cross-warp reduce: every warp, 16 partials, 4 levels.
            float2 t = red[r & 1][lane & 15];
            float Z0 = t.x, S2 = t.y;
#pragma unroll
            for (int o = 8; o > 0; o >>= 1) {
                Z0 += __shfl_xor_sync(0xffffffffu, Z0, o);
                S2 += __shfl_xor_sync(0xffffffffu, S2, o);
            }
            float p0 = rcp_fast(Z0);
            float Z1 = fmaf(-S2, p0, Z0);
            float p1 = rcp_fast(Z1);
            u64 nv0, nv1;
            PACK2(nv0, -p0, -p0);
            PACK2(nv1, -p1, -p1);

            // iteration A (even): nq = -p ; nk += nq ; e = e + nq*e
#pragma unroll
            for (int j = 0; j < PAIRS; j++) {
                u64 nq;
                MUL2(nq, e[j], nv0);
                ADD2(nk[j], nk[j], nq);
                FMA2(e[j], nq, e[j], e[j]);
            }

            if (r < 7) {
                // iteration B (odd) + fold in next body's (Z, S2) partials
                u64 zb = 0ull, sb = 0ull;
#pragma unroll
                for (int j = 0; j < PAIRS; j++) {
                    u64 nq;
                    MUL2(nq, e[j], nv1);
                    ADD2(nk[j], nk[j], nq);
                    FMA2(e[j], nq, e[j], e[j]);
                    ADD2(zb, zb, e[j]);
                    FMA2(sb, e[j], e[j], sb);
                }
                float lo, hi, zf, s2f;
                UNPACK2(lo, hi, zb); zf  = lo + hi;
                UNPACK2(lo, hi, sb); s2f = lo + hi;
                warp_partial_out(zf, s2f, red[(r + 1) & 1], wid, lane);
                __syncthreads();
            } else {
                // final iteration 15: khot accumulate only
#pragma unroll
                for (int j = 0; j < PAIRS; j++) {
                    u64 nq;
                    MUL2(nq, e[j], nv1);
                    ADD2(nk[j], nk[j], nq);
                }
            }
        }

        // ---- store khot = -nk ----
        float4* o4 = (float4*)(out + (size_t)row * NCOL);
#pragma unroll
        for (int c = 0; c < 4; c++) {
            float a0, a1, a2, a3;
            UNPACK2(a0, a1, nk[2 * c]);
            UNPACK2(a2, a3, nk[2 * c + 1]);
            float4 v; v.x = -a0; v.y = -a1; v.z = -a2; v.w = -a3;
            o4[tid + c * THREADS] = v;
        }
    }
}

extern "C" void kernel_launch(void* const* d_in, const int* in_sizes, int n_in,
                              void* d_out, int out_size) {
    const float* scores = (const float*)d_in[0];
    const float* g      = (const float*)d_in[1];
    float* out          = (float*)d_out;
    cudaFuncSetAttribute(subset_op_kernel,
                         cudaFuncAttributeMaxDynamicSharedMemorySize, 2 * NCOL * 4);
    subset_op_kernel<<<GRID, THREADS, 2 * NCOL * 4>>>(scores, g, out);
}

// round 10
// speedup vs baseline: 1.0915x; 1.0915x over previous
#include <cuda_runtime.h>
#include <math_constants.h>
#include <cstdint>

// SubsetOperator soft k-hot (K=16, TAU=1), exp-domain, fixed shift (-10):
//   e = exp(s0-10); repeat K: p = e/Z; khot += p; e *= (1-p)
// State kept RENORMALIZED per 2-iter body: t (=e rescaled, sum ~= 1), so the
// per-body reduced pair (sigA=sum t, sigB=sum t^2) is in (0, 1.2] -> safe u32
// fixed point (scale 2^28) -> redux.sync.add.u32 replaces shuffle butterflies
// at both reduction levels. p = t*rcp(Z_t) is scale-invariant => khot exact.
// Scalars per body: Z0 = sigA, Z1 = sigA - sigB/sigA, p0 = rcp(Z0), p1 = rcp(Z1).

#define ROWS 4096
#define NCOL 8192
#define THREADS 512
#define PAIRS 8
#define GRID 296

typedef unsigned long long u64;
typedef unsigned int u32;

#define MUL2(d,a,b)    asm("mul.rn.f32x2 %0, %1, %2;"     : "=l"(d) : "l"(a), "l"(b))
#define ADD2(d,a,b)    asm("add.rn.f32x2 %0, %1, %2;"     : "=l"(d) : "l"(a), "l"(b))
#define FMA2(d,a,b,c)  asm("fma.rn.f32x2 %0, %1, %2, %3;" : "=l"(d) : "l"(a), "l"(b), "l"(c))
#define PACK2(d,lo,hi)   asm("mov.b64 %0, {%1, %2};" : "=l"(d) : "f"(lo), "f"(hi))
#define UNPACK2(lo,hi,s) asm("mov.b64 {%0, %1}, %2;" : "=f"(lo), "=f"(hi) : "l"(s))

__device__ __forceinline__ float rcp_fast(float x) {
    float r; asm("rcp.approx.f32 %0, %1;" : "=f"(r) : "f"(x)); return r;
}
__device__ __forceinline__ float ex2_fast(float x) {
    float r; asm("ex2.approx.f32 %0, %1;" : "=f"(r) : "f"(x)); return r;
}
__device__ __forceinline__ u32 f2u_rni(float x) {
    u32 u; asm("cvt.rni.u32.f32 %0, %1;" : "=r"(u) : "f"(x)); return u;
}
__device__ __forceinline__ float u2f(u32 u) {
    float x; asm("cvt.rn.f32.u32 %0, %1;" : "=f"(x) : "r"(u)); return x;
}
__device__ __forceinline__ u32 redux_add_u32(u32 v) {
    u32 d; asm("redux.sync.add.u32 %0, %1, 0xffffffff;" : "=r"(d) : "r"(v)); return d;
}

#define SCALE_F 268435456.0f          // 2^28
#define ISCALE_F 3.725290298461914e-9f // 2^-28

__device__ __forceinline__ void cp16(u32 dst, const void* src) {
    asm volatile("cp.async.cg.shared.global [%0], [%1], 16;" :: "r"(dst), "l"(src));
}

__device__ __forceinline__ void prefetch_row(const float* s, const float* gg,
                                             int row, float* tile, int tid, bool valid) {
    if (valid) {
        const float4* s4 = (const float4*)(s + (size_t)row * NCOL);
        const float4* g4 = (const float4*)(gg + (size_t)row * NCOL);
        u32 ds = (u32)__cvta_generic_to_shared(tile);
#pragma unroll
        for (int c = 0; c < 4; c++) {
            cp16(ds + (u32)(tid + c * THREADS) * 16u,                  s4 + tid + c * THREADS);
            cp16(ds + (u32)NCOL * 4u + (u32)(tid + c * THREADS) * 16u, g4 + tid + c * THREADS);
        }
    }
    asm volatile("cp.async.commit_group;");
}

__global__ void __launch_bounds__(THREADS, 2)
subset_op_kernel(const float* __restrict__ scores,
                 const float* __restrict__ g,
                 float* __restrict__ out) {
    extern __shared__ __align__(16) float tile[];     // 64 KB
    __shared__ __align__(16) uint2  redu[2][16];
    __shared__ __align__(16) float2 redf[16];

    const int tid  = threadIdx.x;
    const int lane = tid & 31;
    const int wid  = tid >> 5;
    const float L2E = 1.4426950408889634f;
    const float CC  = -10.0f * L2E;

    int row = blockIdx.x;
    prefetch_row(scores, g, row, tile, tid, true);

    for (; row < ROWS; row += GRID) {
        asm volatile("cp.async.wait_group 0;");
        __syncthreads();

        // ---- prologue: exp + f32 (Z0, S20) reduction (once per row) ----
        u64 t[PAIRS], nk[PAIRS];
        const float4* ts4 = (const float4*)tile;
        const float4* tg4 = (const float4*)(tile + NCOL);
        u64 z2 = 0ull, s22 = 0ull;
#pragma unroll
        for (int c = 0; c < 4; c++) {
            const int i4 = tid + c * THREADS;
            float4 a = ts4[i4];
            float4 b = tg4[i4];
            float e0 = ex2_fast(fmaf(a.x + b.x, L2E, CC));
            float e1 = ex2_fast(fmaf(a.y + b.y, L2E, CC));
            float e2 = ex2_fast(fmaf(a.z + b.z, L2E, CC));
            float e3 = ex2_fast(fmaf(a.w + b.w, L2E, CC));
            PACK2(t[2 * c],     e0, e1);
            PACK2(t[2 * c + 1], e2, e3);
            nk[2 * c] = 0ull; nk[2 * c + 1] = 0ull;
            ADD2(z2, z2, t[2 * c]);
            ADD2(z2, z2, t[2 * c + 1]);
            FMA2(s22, t[2 * c],     t[2 * c],     s22);
            FMA2(s22, t[2 * c + 1], t[2 * c + 1], s22);
        }
        prefetch_row(scores, g, row + GRID, tile, tid, (row + GRID) < ROWS);

        float zf, sf;
        { float lo, hi; UNPACK2(lo, hi, z2);  zf = lo + hi; }
        { float lo, hi; UNPACK2(lo, hi, s22); sf = lo + hi; }
#pragma unroll
        for (int o = 16; o > 0; o >>= 1) {
            zf += __shfl_xor_sync(0xffffffffu, zf, o);
            sf += __shfl_xor_sync(0xffffffffu, sf, o);
        }
        if (lane == 0) { float2 q; q.x = zf; q.y = sf; redf[wid] = q; }
        __syncthreads();
        float Z0r, S0r;
        {
            float2 v = redf[lane & 15];
            float a = v.x, b = v.y;
#pragma unroll
            for (int o = 8; o > 0; o >>= 1) {
                a += __shfl_xor_sync(0xffffffffu, a, o);
                b += __shfl_xor_sync(0xffffffffu, b, o);
            }
            Z0r = a; S0r = b;
        }
        // normalize: t = e * rcp(Z0); entry scalars (in t-units)
        float r0 = rcp_fast(Z0r);
        float sA = Z0r * r0;               // ~1
        float sB = (S0r * r0) * r0;
        {
            u64 r0v; PACK2(r0v, r0, r0);
#pragma unroll
            for (int j = 0; j < PAIRS; j++) MUL2(t[j], t[j], r0v);
        }

        // ---- 8 bodies x 2 iterations ----
#pragma unroll
        for (int r = 0; r < 8; r++) {
            float p0 = rcp_fast(sA);
            float Z1 = fmaf(-sB, p0, sA);
            float p1 = rcp_fast(Z1);
            u64 n0, n1, pv1;
            PACK2(n0, -p0, -p0);
            PACK2(n1, -p1, -p1);
            PACK2(pv1, p1, p1);

            // iteration A: q = -p; nk += q; t += q*t
#pragma unroll
            for (int j = 0; j < PAIRS; j++) {
                u64 q;
                MUL2(q, t[j], n0);
                ADD2(nk[j], nk[j], q);
                FMA2(t[j], q, t[j], t[j]);
            }

            if (r < 7) {
                // iteration B + renormalize t <- t*p1 + fold (sigA, sigB)
                u64 sa2 = 0ull, sb2 = 0ull;
#pragma unroll
                for (int j = 0; j < PAIRS; j++) {
                    u64 q, tn;
                    MUL2(q, t[j], n1);
                    ADD2(nk[j], nk[j], q);
                    FMA2(tn, q, t[j], t[j]);
                    MUL2(t[j], tn, pv1);        // renormalized state
                    ADD2(sa2, sa2, t[j]);
                    FMA2(sb2, t[j], t[j], sb2);
                }
                float aLo, aHi, bLo, bHi;
                UNPACK2(aLo, aHi, sa2);
                UNPACK2(bLo, bHi, sb2);
                u32 ua = f2u_rni((aLo + aHi) * SCALE_F);
                u32 ub = f2u_rni((bLo + bHi) * SCALE_F);
                ua = redux_add_u32(ua);
                ub = redux_add_u32(ub);
                if (lane == 0) { uint2 q; q.x = ua; q.y = ub; redu[r & 1][wid] = q; }
                __syncthreads();
                uint2 v = redu[r & 1][lane & 15];
                u32 xa = (lane < 16) ? v.x : 0u;
                u32 xb = (lane < 16) ? v.y : 0u;
                xa = redux_add_u32(xa);
                xb = redux_add_u32(xb);
                sA = u2f(xa) * ISCALE_F;
                sB = u2f(xb) * ISCALE_F;
            } else {
                // final iteration 15: khot accumulate only
#pragma unroll
                for (int j = 0; j < PAIRS; j++) {
                    u64 q;
                    MUL2(q, t[j], n1);
                    ADD2(nk[j], nk[j], q);
                }
            }
        }

        // ---- store khot = -nk ----
        float4* o4 = (float4*)(out + (size_t)row * NCOL);
#pragma unroll
        for (int c = 0; c < 4; c++) {
            float a0, a1, a2, a3;
            UNPACK2(a0, a1, nk[2 * c]);
            UNPACK2(a2, a3, nk[2 * c + 1]);
            float4 v; v.x = -a0; v.y = -a1; v.z = -a2; v.w = -a3;
            o4[tid + c * THREADS] = v;
        }
        __syncthreads();   // protect redf/redu reuse next row
    }
}

extern "C" void kernel_launch(void* const* d_in, const int* in_sizes, int n_in,
                              void* d_out, int out_size) {
    const float* scores = (const float*)d_in[0];
    const float* g      = (const float*)d_in[1];
    float* out          = (float*)d_out;
    cudaFuncSetAttribute(subset_op_kernel,
                         cudaFuncAttributeMaxDynamicSharedMemorySize, 2 * NCOL * 4);
    subset_op_kernel<<<GRID, THREADS, 2 * NCOL * 4>>>(scores, g, out);
}